// round 1
// baseline (speedup 1.0000x reference)
#include <cuda_runtime.h>
#include <cuda_bf16.h>
#include <cstdint>

#define BATCH 8
#define NPTS  4096
#define CFEAT 128
#define NPOINT 1024
#define NSAMPLE 32
#define COUT  256
#define CIN   131   // 3 + 128

// ---------------- scratch (device globals; no allocation allowed) ----------------
__device__ float g_P[BATCH * NPTS * COUT];          // 33.5 MB  per-point feature GEMM result
__device__ int   g_gidx[BATCH * NPOINT * NSAMPLE];  // ball query indices
__device__ float g_cent[BATCH * NPOINT * 3];        // new_xyz copy for device use
__device__ int   g_fps[BATCH * NPOINT];
__device__ float g_scale[CIN];                      // gamma / sqrt(var+eps)
__device__ float g_Wt[CIN * COUT];                  // W transposed: Wt[c*256 + o] = W[o*131 + c]

// ---------------- init: BN scale + W transpose ----------------
__global__ void init_kernel(const float* __restrict__ W,
                            const float* __restrict__ gamma,
                            const float* __restrict__ var) {
    int idx = blockIdx.x * blockDim.x + threadIdx.x;
    if (idx < CIN * COUT) {
        int o = idx & 255;
        int c = idx >> 8;
        g_Wt[c * COUT + o] = W[o * CIN + c];
    }
    if (idx < CIN) {
        g_scale[idx] = gamma[idx] / sqrtf(var[idx] + 1e-5f);
    }
}

// ---------------- furthest point sampling ----------------
// One block per batch. 256 threads, 16 points each, coords+mind in registers.
// Exact arithmetic (no fma contraction), argmax tie-break = lowest index.
__global__ void __launch_bounds__(256, 1) fps_kernel(const float* __restrict__ xyz,
                                                     float* __restrict__ out_xyz) {
    const int b = blockIdx.x;
    const float* X = xyz + (size_t)b * NPTS * 3;
    const int t    = threadIdx.x;
    const int lane = t & 31;
    const int wid  = t >> 5;
    const int base = t * 16;

    float px[16], py[16], pz[16], mind[16];
#pragma unroll
    for (int i = 0; i < 16; i++) {
        px[i] = X[(base + i) * 3 + 0];
        py[i] = X[(base + i) * 3 + 1];
        pz[i] = X[(base + i) * 3 + 2];
        mind[i] = 1e10f;
    }

    __shared__ unsigned s_wv[8];
    __shared__ int s_wi[8];
    __shared__ int s_last;

    if (t == 0) {
        g_fps[b * NPOINT] = 0;
        float cx = X[0], cy = X[1], cz = X[2];
        g_cent[(size_t)(b * NPOINT) * 3 + 0] = cx;
        g_cent[(size_t)(b * NPOINT) * 3 + 1] = cy;
        g_cent[(size_t)(b * NPOINT) * 3 + 2] = cz;
        out_xyz[(size_t)(b * NPOINT) * 3 + 0] = cx;
        out_xyz[(size_t)(b * NPOINT) * 3 + 1] = cy;
        out_xyz[(size_t)(b * NPOINT) * 3 + 2] = cz;
    }

    int last = 0;
    for (int it = 1; it < NPOINT; ++it) {
        const float qx = X[last * 3 + 0];
        const float qy = X[last * 3 + 1];
        const float qz = X[last * 3 + 2];

        unsigned bb = 0u;   // best mind bits (nonneg float -> bits monotonic)
        int bi = 0;
#pragma unroll
        for (int i = 0; i < 16; i++) {
            float dx = __fsub_rn(px[i], qx);
            float dy = __fsub_rn(py[i], qy);
            float dz = __fsub_rn(pz[i], qz);
            float d  = __fadd_rn(__fadd_rn(__fmul_rn(dx, dx), __fmul_rn(dy, dy)),
                                 __fmul_rn(dz, dz));
            mind[i] = fminf(mind[i], d);
            unsigned mb = __float_as_uint(mind[i]);
            if (mb > bb) { bb = mb; bi = base + i; }   // strict > keeps earliest index
        }

        // warp-level argmax (ties -> lowest lane -> lowest index)
        unsigned wmax = __reduce_max_sync(0xffffffffu, bb);
        unsigned ball = __ballot_sync(0xffffffffu, bb == wmax);
        int src = __ffs(ball) - 1;
        int wbi = __shfl_sync(0xffffffffu, bi, src);
        if (lane == 0) { s_wv[wid] = wmax; s_wi[wid] = wbi; }
        __syncthreads();

        if (wid == 0) {
            unsigned v = (lane < 8) ? s_wv[lane] : 0u;
            unsigned m = __reduce_max_sync(0xffffffffu, v);
            unsigned bl = __ballot_sync(0xffffffffu, (v == m) && (lane < 8));
            int s2 = __ffs(bl) - 1;
            if (lane == 0) {
                int li = s_wi[s2];
                s_last = li;
                g_fps[b * NPOINT + it] = li;
                float cx = X[li * 3 + 0], cy = X[li * 3 + 1], cz = X[li * 3 + 2];
                size_t r = (size_t)(b * NPOINT + it) * 3;
                g_cent[r + 0] = cx; g_cent[r + 1] = cy; g_cent[r + 2] = cz;
                out_xyz[r + 0] = cx; out_xyz[r + 1] = cy; out_xyz[r + 2] = cz;
            }
        }
        __syncthreads();
        last = s_last;
    }
}

// ---------------- ball query: warp per center ----------------
__global__ void __launch_bounds__(1024) ballq_kernel(const float* __restrict__ xyz) {
    const int b    = blockIdx.x >> 5;                       // 256 blocks: 32 per batch
    const int s    = ((blockIdx.x & 31) << 5) + (threadIdx.x >> 5);
    const int lane = threadIdx.x & 31;
    const float* X = xyz + (size_t)b * NPTS * 3;

    const size_t g = (size_t)b * NPOINT + s;
    const float cx = g_cent[g * 3 + 0];
    const float cy = g_cent[g * 3 + 1];
    const float cz = g_cent[g * 3 + 2];
    int* out = g_gidx + g * NSAMPLE;

    // radius^2 exactly as JAX: python double 0.1*0.1 weak-cast to f32
    const float R2 = (float)(0.1 * 0.1);

    int cnt = 0;
    int first = -1;
    for (int basej = 0; basej < NPTS; basej += 32) {
        int j = basej + lane;
        float dx = __fsub_rn(cx, X[j * 3 + 0]);
        float dy = __fsub_rn(cy, X[j * 3 + 1]);
        float dz = __fsub_rn(cz, X[j * 3 + 2]);
        float d2 = __fadd_rn(__fadd_rn(__fmul_rn(dx, dx), __fmul_rn(dy, dy)),
                             __fmul_rn(dz, dz));
        bool valid = d2 < R2;
        unsigned mask = __ballot_sync(0xffffffffu, valid);
        if (first < 0 && mask) first = basej + __ffs(mask) - 1;
        if (valid) {
            int pos = cnt + __popc(mask & ((1u << lane) - 1u));
            if (pos < NSAMPLE) out[pos] = j;
        }
        cnt += __popc(mask);
        if (cnt >= NSAMPLE) break;
    }
    if (lane >= cnt && lane < NSAMPLE) out[lane] = first;   // cnt>=1 always (center itself)
}

// ---------------- per-point feature GEMM: P = relu(bn(feat)) @ Wfeat^T ----------------
// M = 32768, K = 128, N = 256.  64x64x16 tile, 256 threads, 4x4 micro-tile.
__global__ void __launch_bounds__(256) gemmP_kernel(const float* __restrict__ feat,
                                                    const float* __restrict__ bn_mean,
                                                    const float* __restrict__ bn_beta) {
    __shared__ float As[16][68];   // As[k][m], padded
    __shared__ float Bs[16][68];   // Bs[k][n], padded

    const int bm = blockIdx.x * 64;
    const int bn = blockIdx.y * 64;
    const int tid = threadIdx.x;

    const int row = tid >> 4;          // 0..15 -> m micro base row*4
    const int col = tid & 15;          // 0..15 -> n micro base col*4
    const int lm  = tid >> 2;          // A-load row 0..63
    const int lk4 = (tid & 3) * 4;     // A-load k offset
    const int kb  = tid >> 4;          // B-load k row 0..15
    const int nb4 = (tid & 15) * 4;    // B-load n offset

    float acc[4][4];
#pragma unroll
    for (int i = 0; i < 4; i++)
#pragma unroll
        for (int j = 0; j < 4; j++) acc[i][j] = 0.f;

    for (int k0 = 0; k0 < CFEAT; k0 += 16) {
        float4 a4 = *(const float4*)(feat + (size_t)(bm + lm) * CFEAT + k0 + lk4);
        float av[4] = {a4.x, a4.y, a4.z, a4.w};
#pragma unroll
        for (int i = 0; i < 4; i++) {
            int c = k0 + lk4 + i + 3;   // channel in concat space
            float v = (av[i] - bn_mean[c]) * g_scale[c] + bn_beta[c];
            As[lk4 + i][lm] = fmaxf(v, 0.f);
        }
        float4 b4 = *(const float4*)(g_Wt + (size_t)(k0 + kb + 3) * COUT + bn + nb4);
        *(float4*)&Bs[kb][nb4] = b4;
        __syncthreads();

#pragma unroll
        for (int k = 0; k < 16; k++) {
            float4 a = *(float4*)&As[k][row * 4];
            float4 bq = *(float4*)&Bs[k][col * 4];
            float ar[4] = {a.x, a.y, a.z, a.w};
            float br[4] = {bq.x, bq.y, bq.z, bq.w};
#pragma unroll
            for (int i = 0; i < 4; i++)
#pragma unroll
                for (int j = 0; j < 4; j++) acc[i][j] += ar[i] * br[j];
        }
        __syncthreads();
    }

#pragma unroll
    for (int i = 0; i < 4; i++) {
        float4 o4 = make_float4(acc[i][0], acc[i][1], acc[i][2], acc[i][3]);
        *(float4*)(g_P + (size_t)(bm + row * 4 + i) * COUT + bn + col * 4) = o4;
    }
}

// ---------------- combine: gather P + xyz part, max over samples, bias, transpose ----------------
__global__ void __launch_bounds__(256) combine_kernel(const float* __restrict__ xyz,
                                                      const float* __restrict__ bias,
                                                      const float* __restrict__ bn_mean,
                                                      const float* __restrict__ bn_beta,
                                                      float* __restrict__ out_feat) {
    const int g = blockIdx.x;          // 0..8191
    const int b = g >> 10;
    const int s = g & 1023;
    const int o = threadIdx.x;         // 0..255

    __shared__ float t0[NSAMPLE], t1[NSAMPLE], t2[NSAMPLE];
    __shared__ int sidx[NSAMPLE];

    if (o < NSAMPLE) {
        int id = g_gidx[(size_t)g * NSAMPLE + o];
        sidx[o] = id;
        const float* Xp = xyz + ((size_t)b * NPTS + id) * 3;
        float cx = g_cent[(size_t)g * 3 + 0];
        float cy = g_cent[(size_t)g * 3 + 1];
        float cz = g_cent[(size_t)g * 3 + 2];
        float gx = __fsub_rn(Xp[0], cx);
        float gy = __fsub_rn(Xp[1], cy);
        float gz = __fsub_rn(Xp[2], cz);
        t0[o] = fmaxf((gx - bn_mean[0]) * g_scale[0] + bn_beta[0], 0.f);
        t1[o] = fmaxf((gy - bn_mean[1]) * g_scale[1] + bn_beta[1], 0.f);
        t2[o] = fmaxf((gz - bn_mean[2]) * g_scale[2] + bn_beta[2], 0.f);
    }
    __syncthreads();

    const float w0 = g_Wt[0 * COUT + o];
    const float w1 = g_Wt[1 * COUT + o];
    const float w2 = g_Wt[2 * COUT + o];
    const float* Pb = g_P + (size_t)b * NPTS * COUT;

    float acc = -3.402823466e+38f;
#pragma unroll 8
    for (int k = 0; k < NSAMPLE; k++) {
        float v = Pb[(size_t)sidx[k] * COUT + o];
        v = fmaf(w0, t0[k], v);
        v = fmaf(w1, t1[k], v);
        v = fmaf(w2, t2[k], v);
        acc = fmaxf(acc, v);
    }
    out_feat[((size_t)b * COUT + o) * NPOINT + s] = acc + bias[o];
}

// ---------------- launch ----------------
extern "C" void kernel_launch(void* const* d_in, const int* in_sizes, int n_in,
                              void* d_out, int out_size) {
    const float* xyz   = (const float*)d_in[0];
    const float* feat  = (const float*)d_in[1];
    const float* W     = (const float*)d_in[2];
    const float* bias  = (const float*)d_in[3];
    const float* gamma = (const float*)d_in[4];
    const float* beta  = (const float*)d_in[5];
    const float* mean  = (const float*)d_in[6];
    const float* var   = (const float*)d_in[7];

    float* out = (float*)d_out;
    float* out_feat = out + ((size_t)out_size - (size_t)BATCH * COUT * NPOINT);

    init_kernel<<<(CIN * COUT + 255) / 256, 256>>>(W, gamma, var);
    fps_kernel<<<BATCH, 256>>>(xyz, out);
    ballq_kernel<<<BATCH * 32, 1024>>>(xyz);
    gemmP_kernel<<<dim3((BATCH * NPTS) / 64, COUT / 64), 256>>>(feat, mean, beta);
    combine_kernel<<<BATCH * NPOINT, 256>>>(xyz, bias, mean, beta, out_feat);
}

// round 2
// speedup vs baseline: 1.2558x; 1.2558x over previous
#include <cuda_runtime.h>
#include <cuda_bf16.h>
#include <cstdint>

#define BATCH 8
#define NPTS  4096
#define CFEAT 128
#define NPOINT 1024
#define NSAMPLE 32
#define COUT  256
#define CIN   131   // 3 + 128

// ---------------- scratch (device globals; no allocation allowed) ----------------
__device__ float g_P[BATCH * NPTS * COUT];          // 33.5 MB  per-point feature GEMM result
__device__ int   g_gidx[BATCH * NPOINT * NSAMPLE];  // ball query indices
__device__ float g_cent[BATCH * NPOINT * 3];        // new_xyz copy for device use
__device__ float g_scale[CIN];                      // gamma / sqrt(var+eps)
__device__ float g_Wt[CIN * COUT];                  // W transposed: Wt[c*256 + o] = W[o*131 + c]

// ---------------- packed f32x2 helpers (bit-identical to scalar rn ops) ----------------
__device__ __forceinline__ unsigned long long f2_add(unsigned long long a, unsigned long long b) {
    unsigned long long r;
    asm("add.rn.f32x2 %0,%1,%2;" : "=l"(r) : "l"(a), "l"(b));
    return r;
}
__device__ __forceinline__ unsigned long long f2_mul(unsigned long long a, unsigned long long b) {
    unsigned long long r;
    asm("mul.rn.f32x2 %0,%1,%2;" : "=l"(r) : "l"(a), "l"(b));
    return r;
}
__device__ __forceinline__ unsigned long long f2_pack(float lo, float hi) {
    unsigned long long r;
    asm("mov.b64 %0,{%1,%2};" : "=l"(r) : "f"(lo), "f"(hi));
    return r;
}
__device__ __forceinline__ void f2_unpack(unsigned long long v, float& lo, float& hi) {
    asm("mov.b64 {%0,%1},%2;" : "=f"(lo), "=f"(hi) : "l"(v));
}

// ---------------- init: BN scale + W transpose ----------------
__global__ void init_kernel(const float* __restrict__ W,
                            const float* __restrict__ gamma,
                            const float* __restrict__ var) {
    int idx = blockIdx.x * blockDim.x + threadIdx.x;
    if (idx < CIN * COUT) {
        int o = idx & 255;
        int c = idx >> 8;
        g_Wt[c * COUT + o] = W[o * CIN + c];
    }
    if (idx < CIN) {
        g_scale[idx] = gamma[idx] / sqrtf(var[idx] + 1e-5f);
    }
}

// ---------------- furthest point sampling ----------------
// One block per batch. 128 threads, 32 points each (16 f32x2 pairs) in registers.
// Exact arithmetic (packed rn ops == scalar rn ops), argmax tie-break = lowest index.
// Single __syncthreads per iteration via parity-double-buffered partials.
__global__ void __launch_bounds__(128, 1) fps_kernel(const float* __restrict__ xyz,
                                                     float* __restrict__ out_xyz) {
    const int b = blockIdx.x;
    const float* X = xyz + (size_t)b * NPTS * 3;
    const int t    = threadIdx.x;
    const int lane = t & 31;
    const int wid  = t >> 5;
    const int base = t * 32;

    unsigned long long PX[16], PY[16], PZ[16];
    float mind[32];
#pragma unroll
    for (int i = 0; i < 16; i++) {
        int p0 = base + 2 * i;
        float x0 = X[p0 * 3 + 0], y0 = X[p0 * 3 + 1], z0 = X[p0 * 3 + 2];
        float x1 = X[p0 * 3 + 3], y1 = X[p0 * 3 + 4], z1 = X[p0 * 3 + 5];
        PX[i] = f2_pack(x0, x1);
        PY[i] = f2_pack(y0, y1);
        PZ[i] = f2_pack(z0, z1);
        mind[2 * i] = 1e10f;
        mind[2 * i + 1] = 1e10f;
    }

    __shared__ unsigned long long s_part[2][4];

    float qx = X[0], qy = X[1], qz = X[2];
    if (t == 0) {
        size_t r = (size_t)(b * NPOINT) * 3;
        g_cent[r + 0] = qx; g_cent[r + 1] = qy; g_cent[r + 2] = qz;
        out_xyz[r + 0] = qx; out_xyz[r + 1] = qy; out_xyz[r + 2] = qz;
    }

    for (int it = 1; it < NPOINT; ++it) {
        const unsigned long long nqx = f2_pack(-qx, -qx);
        const unsigned long long nqy = f2_pack(-qy, -qy);
        const unsigned long long nqz = f2_pack(-qz, -qz);

        unsigned bb = 0u;   // best mind bits (nonneg float -> bits monotonic)
        int bi = 0;
#pragma unroll
        for (int i = 0; i < 16; i++) {
            unsigned long long dx = f2_add(PX[i], nqx);
            unsigned long long dy = f2_add(PY[i], nqy);
            unsigned long long dz = f2_add(PZ[i], nqz);
            unsigned long long s  = f2_add(f2_add(f2_mul(dx, dx), f2_mul(dy, dy)),
                                           f2_mul(dz, dz));
            float s0, s1;
            f2_unpack(s, s0, s1);
            mind[2 * i]     = fminf(mind[2 * i], s0);
            mind[2 * i + 1] = fminf(mind[2 * i + 1], s1);
            unsigned m0 = __float_as_uint(mind[2 * i]);
            if (m0 > bb) { bb = m0; bi = base + 2 * i; }       // strict > keeps earliest index
            unsigned m1 = __float_as_uint(mind[2 * i + 1]);
            if (m1 > bb) { bb = m1; bi = base + 2 * i + 1; }
        }

        // warp argmax (ties -> lowest lane -> lowest index)
        unsigned wmax = __reduce_max_sync(0xffffffffu, bb);
        unsigned ball = __ballot_sync(0xffffffffu, bb == wmax);
        int src = __ffs(ball) - 1;
        int wbi = __shfl_sync(0xffffffffu, bi, src);
        if (lane == 0)
            s_part[it & 1][wid] = ((unsigned long long)wmax << 32) | (unsigned)(~wbi);
        __syncthreads();

        // every thread resolves the block winner itself (no 2nd barrier)
        unsigned long long w0 = s_part[it & 1][0];
        unsigned long long w1 = s_part[it & 1][1];
        unsigned long long w2 = s_part[it & 1][2];
        unsigned long long w3 = s_part[it & 1][3];
        unsigned long long win = w0;
        if (w1 > win) win = w1;
        if (w2 > win) win = w2;
        if (w3 > win) win = w3;
        int li = (int)(~(unsigned)win);

        qx = X[li * 3 + 0]; qy = X[li * 3 + 1]; qz = X[li * 3 + 2];
        if (t == 0) {
            size_t r = (size_t)(b * NPOINT + it) * 3;
            g_cent[r + 0] = qx; g_cent[r + 1] = qy; g_cent[r + 2] = qz;
            out_xyz[r + 0] = qx; out_xyz[r + 1] = qy; out_xyz[r + 2] = qz;
        }
    }
}

// ---------------- ball query: warp per center ----------------
__global__ void __launch_bounds__(1024) ballq_kernel(const float* __restrict__ xyz) {
    const int b    = blockIdx.x >> 5;                       // 256 blocks: 32 per batch
    const int s    = ((blockIdx.x & 31) << 5) + (threadIdx.x >> 5);
    const int lane = threadIdx.x & 31;
    const float* X = xyz + (size_t)b * NPTS * 3;

    const size_t g = (size_t)b * NPOINT + s;
    const float cx = g_cent[g * 3 + 0];
    const float cy = g_cent[g * 3 + 1];
    const float cz = g_cent[g * 3 + 2];
    int* out = g_gidx + g * NSAMPLE;

    // radius^2 exactly as JAX: python double 0.1*0.1 weak-cast to f32
    const float R2 = (float)(0.1 * 0.1);

    int cnt = 0;
    int first = -1;
    for (int basej = 0; basej < NPTS; basej += 32) {
        int j = basej + lane;
        float dx = __fsub_rn(cx, X[j * 3 + 0]);
        float dy = __fsub_rn(cy, X[j * 3 + 1]);
        float dz = __fsub_rn(cz, X[j * 3 + 2]);
        float d2 = __fadd_rn(__fadd_rn(__fmul_rn(dx, dx), __fmul_rn(dy, dy)),
                             __fmul_rn(dz, dz));
        bool valid = d2 < R2;
        unsigned mask = __ballot_sync(0xffffffffu, valid);
        if (first < 0 && mask) first = basej + __ffs(mask) - 1;
        if (valid) {
            int pos = cnt + __popc(mask & ((1u << lane) - 1u));
            if (pos < NSAMPLE) out[pos] = j;
        }
        cnt += __popc(mask);
        if (cnt >= NSAMPLE) break;
    }
    if (lane >= cnt && lane < NSAMPLE) out[lane] = first;   // cnt>=1 always (center itself)
}

// ---------------- per-point feature GEMM: P = relu(bn(feat)) @ Wfeat^T ----------------
// M = 32768, K = 128, N = 256.  64x64x16 tile, 256 threads, 4x4 micro-tile.
__global__ void __launch_bounds__(256) gemmP_kernel(const float* __restrict__ feat,
                                                    const float* __restrict__ bn_mean,
                                                    const float* __restrict__ bn_beta) {
    __shared__ float As[16][68];   // As[k][m], padded
    __shared__ float Bs[16][68];   // Bs[k][n], padded

    const int bm = blockIdx.x * 64;
    const int bn = blockIdx.y * 64;
    const int tid = threadIdx.x;

    const int row = tid >> 4;          // 0..15 -> m micro base row*4
    const int col = tid & 15;          // 0..15 -> n micro base col*4
    const int lm  = tid >> 2;          // A-load row 0..63
    const int lk4 = (tid & 3) * 4;     // A-load k offset
    const int kb  = tid >> 4;          // B-load k row 0..15
    const int nb4 = (tid & 15) * 4;    // B-load n offset

    float acc[4][4];
#pragma unroll
    for (int i = 0; i < 4; i++)
#pragma unroll
        for (int j = 0; j < 4; j++) acc[i][j] = 0.f;

    for (int k0 = 0; k0 < CFEAT; k0 += 16) {
        float4 a4 = *(const float4*)(feat + (size_t)(bm + lm) * CFEAT + k0 + lk4);
        float av[4] = {a4.x, a4.y, a4.z, a4.w};
#pragma unroll
        for (int i = 0; i < 4; i++) {
            int c = k0 + lk4 + i + 3;   // channel in concat space
            float v = (av[i] - bn_mean[c]) * g_scale[c] + bn_beta[c];
            As[lk4 + i][lm] = fmaxf(v, 0.f);
        }
        float4 b4 = *(const float4*)(g_Wt + (size_t)(k0 + kb + 3) * COUT + bn + nb4);
        *(float4*)&Bs[kb][nb4] = b4;
        __syncthreads();

#pragma unroll
        for (int k = 0; k < 16; k++) {
            float4 a = *(float4*)&As[k][row * 4];
            float4 bq = *(float4*)&Bs[k][col * 4];
            float ar[4] = {a.x, a.y, a.z, a.w};
            float br[4] = {bq.x, bq.y, bq.z, bq.w};
#pragma unroll
            for (int i = 0; i < 4; i++)
#pragma unroll
                for (int j = 0; j < 4; j++) acc[i][j] += ar[i] * br[j];
        }
        __syncthreads();
    }

#pragma unroll
    for (int i = 0; i < 4; i++) {
        float4 o4 = make_float4(acc[i][0], acc[i][1], acc[i][2], acc[i][3]);
        *(float4*)(g_P + (size_t)(bm + row * 4 + i) * COUT + bn + col * 4) = o4;
    }
}

// ---------------- combine: gather P + xyz part, max over samples, bias, transpose ----------------
__global__ void __launch_bounds__(256) combine_kernel(const float* __restrict__ xyz,
                                                      const float* __restrict__ bias,
                                                      const float* __restrict__ bn_mean,
                                                      const float* __restrict__ bn_beta,
                                                      float* __restrict__ out_feat) {
    const int g = blockIdx.x;          // 0..8191
    const int b = g >> 10;
    const int s = g & 1023;
    const int o = threadIdx.x;         // 0..255

    __shared__ float t0[NSAMPLE], t1[NSAMPLE], t2[NSAMPLE];
    __shared__ int sidx[NSAMPLE];

    if (o < NSAMPLE) {
        int id = g_gidx[(size_t)g * NSAMPLE + o];
        sidx[o] = id;
        const float* Xp = xyz + ((size_t)b * NPTS + id) * 3;
        float cx = g_cent[(size_t)g * 3 + 0];
        float cy = g_cent[(size_t)g * 3 + 1];
        float cz = g_cent[(size_t)g * 3 + 2];
        float gx = __fsub_rn(Xp[0], cx);
        float gy = __fsub_rn(Xp[1], cy);
        float gz = __fsub_rn(Xp[2], cz);
        t0[o] = fmaxf((gx - bn_mean[0]) * g_scale[0] + bn_beta[0], 0.f);
        t1[o] = fmaxf((gy - bn_mean[1]) * g_scale[1] + bn_beta[1], 0.f);
        t2[o] = fmaxf((gz - bn_mean[2]) * g_scale[2] + bn_beta[2], 0.f);
    }
    __syncthreads();

    const float w0 = g_Wt[0 * COUT + o];
    const float w1 = g_Wt[1 * COUT + o];
    const float w2 = g_Wt[2 * COUT + o];
    const float* Pb = g_P + (size_t)b * NPTS * COUT;

    float acc = -3.402823466e+38f;
#pragma unroll 8
    for (int k = 0; k < NSAMPLE; k++) {
        float v = Pb[(size_t)sidx[k] * COUT + o];
        v = fmaf(w0, t0[k], v);
        v = fmaf(w1, t1[k], v);
        v = fmaf(w2, t2[k], v);
        acc = fmaxf(acc, v);
    }
    out_feat[((size_t)b * COUT + o) * NPOINT + s] = acc + bias[o];
}

// ---------------- launch ----------------
extern "C" void kernel_launch(void* const* d_in, const int* in_sizes, int n_in,
                              void* d_out, int out_size) {
    const float* xyz   = (const float*)d_in[0];
    const float* feat  = (const float*)d_in[1];
    const float* W     = (const float*)d_in[2];
    const float* bias  = (const float*)d_in[3];
    const float* gamma = (const float*)d_in[4];
    const float* beta  = (const float*)d_in[5];
    const float* mean  = (const float*)d_in[6];
    const float* var   = (const float*)d_in[7];

    float* out = (float*)d_out;
    float* out_feat = out + ((size_t)out_size - (size_t)BATCH * COUT * NPOINT);

    init_kernel<<<(CIN * COUT + 255) / 256, 256>>>(W, gamma, var);
    fps_kernel<<<BATCH, 128>>>(xyz, out);
    ballq_kernel<<<BATCH * 32, 1024>>>(xyz);
    gemmP_kernel<<<dim3((BATCH * NPTS) / 64, COUT / 64), 256>>>(feat, mean, beta);
    combine_kernel<<<BATCH * NPOINT, 256>>>(xyz, bias, mean, beta, out_feat);
}